// round 14
// baseline (speedup 1.0000x reference)
#include <cuda_runtime.h>
#include <cuda_fp16.h>
#include <cstdint>

// Problem dims: B=4, S=4096, D=4096, E=64, K=2
#define NTOK 16384
#define DDIM 4096
#define NEXP 64
#define TPC  128                 // tokens per CTA
#define NCTA (NTOK / TPC)        // 128
#define THREADS 128              // 4 warps, each 32 tokens x 64 experts
#define KC   64                  // K per chunk
#define NCHUNK (DDIM / KC)       // 64
#define NSTAGE 4

// Output layout (flattened f32): idx[2N], scores[2N], probs[64N], zloss[1], imp[64], load[64]
#define OFF_IDX     0
#define OFF_SCORES  (NTOK * 2)
#define OFF_PROBS   (NTOK * 4)
#define OFF_ZLOSS   (NTOK * 4 + NTOK * NEXP)
#define OFF_IMP     (OFF_ZLOSS + 1)
#define OFF_LOAD    (OFF_IMP + NEXP)

// smem staging per stage: A fp32 (pitch 288B) + B fp16 2 levels (pitch 144B)
#define APITCH 288
#define ASTAGE (TPC * APITCH)        // 36864
#define BPITCH 144
#define LEVSZ  (NEXP * BPITCH)       // 9216
#define BSTAGE (2 * LEVSZ)           // 18432
#define STAGE  (ASTAGE + BSTAGE)     // 55296
#define SMEM_TOTAL (NSTAGE * STAGE)  // 221184

#define SCALE   4096.0f              // 2^12 residual scaling
#define INVSCALE (1.0f / 4096.0f)

// Scratch globals
__device__ unsigned short g_Wh[NEXP * DDIM];
__device__ unsigned short g_Wl[NEXP * DDIM];   // fp16(2^12 * residual)
__device__ float g_acc[2 * NEXP + 1];
__device__ unsigned int g_done;

// ---------------------------------------------------------------------------
__device__ __forceinline__ uint32_t smem_u32(const void* p) {
    uint32_t a;
    asm("{ .reg .u64 t; cvta.to.shared.u64 t, %1; cvt.u32.u64 %0, t; }" : "=r"(a) : "l"(p));
    return a;
}

#define CPA16(sm, gp) \
    asm volatile("cp.async.cg.shared.global [%0], [%1], 16;" :: "r"(sm), "l"(gp))
#define CPC()  asm volatile("cp.async.commit_group;" ::: "memory")
#define CPW2() asm volatile("cp.async.wait_group 2;" ::: "memory")
#define CPW1() asm volatile("cp.async.wait_group 1;" ::: "memory")
#define CPW0() asm volatile("cp.async.wait_group 0;" ::: "memory")

#define LDSM4(R, a) \
    asm volatile("ldmatrix.sync.aligned.m8n8.x4.shared.b16 {%0,%1,%2,%3}, [%4];" \
        : "=r"((R)[0]), "=r"((R)[1]), "=r"((R)[2]), "=r"((R)[3]) : "r"(a))

#define MMA(C, A, B0, B1) \
    asm volatile("mma.sync.aligned.m16n8k16.row.col.f32.f16.f16.f32 " \
        "{%0,%1,%2,%3}, {%4,%5,%6,%7}, {%8,%9}, {%0,%1,%2,%3};" \
        : "+f"((C)[0]), "+f"((C)[1]), "+f"((C)[2]), "+f"((C)[3]) \
        : "r"((A)[0]), "r"((A)[1]), "r"((A)[2]), "r"((A)[3]), "r"(B0), "r"(B1))

__device__ __forceinline__ void splitAx(float2 v, unsigned& h, unsigned& l) {
    __half2 hh = __float22half2_rn(v);
    float2 back = __half22float2(hh);
    float2 r = make_float2((v.x - back.x) * SCALE, (v.y - back.y) * SCALE);
    __half2 ll = __float22half2_rn(r);
    h = *reinterpret_cast<unsigned*>(&hh);
    l = *reinterpret_cast<unsigned*>(&ll);
}

__device__ __forceinline__ bool better(float v1, int i1, float v2, int i2) {
    return (v1 > v2) || (v1 == v2 && i1 < i2);
}

// ---------------------------------------------------------------------------
// Kernel 1: split W into fp16 high + scaled-residual levels; zero accumulators
// ---------------------------------------------------------------------------
__global__ void prep_kernel(const float* __restrict__ W) {
    int i = blockIdx.x * 256 + threadIdx.x;
    if (i < NEXP * DDIM) {
        float w = W[i];
        __half h = __float2half_rn(w);
        float r = (w - __half2float(h)) * SCALE;
        __half l = __float2half_rn(r);
        g_Wh[i] = *reinterpret_cast<unsigned short*>(&h);
        g_Wl[i] = *reinterpret_cast<unsigned short*>(&l);
    }
    if (i < 2 * NEXP + 1) g_acc[i] = 0.0f;
    if (i == 0) g_done = 0u;
}

// ---------------------------------------------------------------------------
// per-token-row routing epilogue (quad of 4 lanes owns one row of 64 logits)
// ---------------------------------------------------------------------------
__device__ __forceinline__ void row_epilogue(const float v[16], float p[16],
                                             int token, int qc, int lane,
                                             float* __restrict__ out,
                                             float* s_cnt, float& zz) {
    float mx = v[0];
#pragma unroll
    for (int i = 1; i < 16; ++i) mx = fmaxf(mx, v[i]);
    mx = fmaxf(mx, __shfl_xor_sync(0xffffffffu, mx, 1));
    mx = fmaxf(mx, __shfl_xor_sync(0xffffffffu, mx, 2));
    float s = 0.0f;
#pragma unroll
    for (int i = 0; i < 16; ++i) { p[i] = __expf(v[i] - mx); s += p[i]; }
    s += __shfl_xor_sync(0xffffffffu, s, 1);
    s += __shfl_xor_sync(0xffffffffu, s, 2);
    const float inv = 1.0f / s;
#pragma unroll
    for (int i = 0; i < 16; ++i) p[i] *= inv;
    float* po = out + OFF_PROBS + (size_t)token * NEXP;
#pragma unroll
    for (int j = 0; j < 8; ++j)
        *reinterpret_cast<float2*>(po + j * 8 + qc) = make_float2(p[2 * j], p[2 * j + 1]);
    // local top-2 (ascending col order; strict > keeps lowest index on ties)
    float av = -3.4e38f, bv = -3.4e38f; int ai = 0, bi = 0;
#pragma unroll
    for (int j = 0; j < 8; ++j)
#pragma unroll
        for (int i = 0; i < 2; ++i) {
            float val = v[j * 2 + i];
            int col = j * 8 + qc + i;
            if (val > av)      { bv = av; bi = ai; av = val; ai = col; }
            else if (val > bv) { bv = val; bi = col; }
        }
#pragma unroll
    for (int o = 1; o <= 2; o <<= 1) {
        float av2 = __shfl_xor_sync(0xffffffffu, av, o);
        int   ai2 = __shfl_xor_sync(0xffffffffu, ai, o);
        float bv2 = __shfl_xor_sync(0xffffffffu, bv, o);
        int   bi2 = __shfl_xor_sync(0xffffffffu, bi, o);
        if (better(av2, ai2, av, ai)) {
            bool s2 = better(bv2, bi2, av, ai);
            float nbv = s2 ? bv2 : av; int nbi = s2 ? bi2 : ai;
            av = av2; ai = ai2; bv = nbv; bi = nbi;
        } else if (better(av2, ai2, bv, bi)) { bv = av2; bi = ai2; }
    }
    if ((lane & 3) == 0) {
        float ex  = __expf(bv - av);
        float sc0 = 1.0f / (1.0f + ex);
        out[OFF_IDX + token * 2]        = (float)ai;
        out[OFF_IDX + token * 2 + 1]    = (float)bi;
        out[OFF_SCORES + token * 2]     = sc0;
        out[OFF_SCORES + token * 2 + 1] = ex * sc0;
        atomicAdd(&s_cnt[ai], 1.0f);
        atomicAdd(&s_cnt[bi], 1.0f);
    }
    float z = mx + __logf(s);
    zz += z * z;
}

// ---------------------------------------------------------------------------
// Kernel 2: fused 3-way fp16-split GEMM (mma.sync) + routing epilogue.
// 128 threads, 4 warps, warp = 32 tokens x 64 experts (2 m16 tiles):
// halves the per-SM B-fragment smem traffic vs 8 warps of M=16.
// 4-stage cp.async ring, single __syncthreads per chunk (proven R8/R10).
// ---------------------------------------------------------------------------
__global__ void __launch_bounds__(THREADS, 1)
router_kernel(const float* __restrict__ x, float* __restrict__ out) {
    extern __shared__ __align__(16) char smem[];
    const uint32_t sb = smem_u32(smem);
    const int tid = threadIdx.x, w = tid >> 5, lane = tid & 31;
    const int g = lane >> 2, qc = (lane & 3) * 2;
    const int token0 = blockIdx.x * TPC;

    const char* xbytes = reinterpret_cast<const char*>(x);
    const char* whb = reinterpret_cast<const char*>(g_Wh);
    const char* wlb = reinterpret_cast<const char*>(g_Wl);

    // ldmatrix per-lane address component (layout proven rounds 3/5/8/10)
    const int n_in = (lane & 7) | ((lane & 16) >> 1);
    const int lmoff = n_in * BPITCH + ((lane & 8) << 1);

    // A fragment smem addresses: warp rows w*32 + {g, g+8, g+16, g+24}
    const uint32_t arow0 = sb + (uint32_t)(w * 32 + g) * APITCH + (uint32_t)qc * 4;

    float C[2][8][4], Clo[2][8][4];
#pragma unroll
    for (int m = 0; m < 2; ++m)
#pragma unroll
        for (int j = 0; j < 8; ++j)
#pragma unroll
            for (int i = 0; i < 4; ++i) { C[m][j][i] = 0.0f; Clo[m][j][i] = 0.0f; }

    // A: 2048 16B segs/stage, 16/thread. B: 1024 segs (2 levels), 8/thread.
#define ISSUE_STAGE(sidx, k0)                                                        \
    do {                                                                             \
        const uint32_t _stg = sb + (uint32_t)(sidx) * STAGE;                         \
        const uint32_t _sbB = _stg + ASTAGE;                                         \
        _Pragma("unroll")                                                            \
        for (int ps = 0; ps < 16; ++ps) {                                            \
            int idx = tid + ps * 128;                                                \
            int row = idx >> 4, seg = idx & 15;                                      \
            CPA16(_stg + row * APITCH + seg * 16,                                    \
                  xbytes + ((size_t)(token0 + row) * DDIM + (k0) + seg * 4) * 4);    \
        }                                                                            \
        _Pragma("unroll")                                                            \
        for (int ps = 0; ps < 8; ++ps) {                                             \
            int idx = tid + ps * 128;                                                \
            int lev = idx >> 9, rem = idx & 511, row = rem >> 3, seg = rem & 7;      \
            const char* src = (lev == 0 ? whb : wlb)                                 \
                              + ((size_t)row * DDIM + (k0) + seg * 8) * 2;           \
            CPA16(_sbB + lev * LEVSZ + row * BPITCH + seg * 16, src);                \
        }                                                                            \
        CPC();                                                                       \
    } while (0)

    // prologue: stages 0, 1
    ISSUE_STAGE(0, 0);
    ISSUE_STAGE(1, KC);

#pragma unroll 1
    for (int c = 0; c < NCHUNK; ++c) {
        const int bufc = c & 3;
        // fill buffer (c+2)%4: held stage c-2, fully consumed before iter c-1's
        // barrier -> safe with the single sync below (proven R8/R10).
        if (c + 2 < NCHUNK) {
            ISSUE_STAGE((c + 2) & 3, (c + 2) * KC);
            CPW2();
        } else if (c + 1 < NCHUNK) {
            CPW1();
        } else {
            CPW0();
        }
        __syncthreads();

        const uint32_t stg = sb + (uint32_t)bufc * STAGE;
        const uint32_t a0 = arow0 + (uint32_t)bufc * STAGE;
        const uint32_t bbase = stg + ASTAGE + lmoff;

#pragma unroll
        for (int ks = 0; ks < 4; ++ks) {
            const uint32_t ka = (uint32_t)(ks * 64);
            // A fragments for both m16 tiles (rows g/g+8 and g+16/g+24)
            unsigned ah[2][4], al[2][4];
#pragma unroll
            for (int m = 0; m < 2; ++m) {
                const uint32_t am = a0 + (uint32_t)(m * 16) * APITCH + ka;
                float2 f0, f1, f2, f3;
                asm volatile("ld.shared.v2.f32 {%0,%1}, [%2];" : "=f"(f0.x), "=f"(f0.y) : "r"(am));
                asm volatile("ld.shared.v2.f32 {%0,%1}, [%2];" : "=f"(f1.x), "=f"(f1.y) : "r"(am + 8u * APITCH));
                asm volatile("ld.shared.v2.f32 {%0,%1}, [%2];" : "=f"(f2.x), "=f"(f2.y) : "r"(am + 32));
                asm volatile("ld.shared.v2.f32 {%0,%1}, [%2];" : "=f"(f3.x), "=f"(f3.y) : "r"(am + 8u * APITCH + 32));
                splitAx(f0, ah[m][0], al[m][0]);
                splitAx(f1, ah[m][1], al[m][1]);
                splitAx(f2, ah[m][2], al[m][2]);
                splitAx(f3, ah[m][3], al[m][3]);
            }

            const uint32_t ba = bbase + ks * 32;
            // hi-level B, C sweeps for both m-tiles (reuse bh across 32 MMAs)
            unsigned bh[16];
#pragma unroll
            for (int p = 0; p < 4; ++p) LDSM4(bh + 4 * p, ba + p * (16 * BPITCH));
#pragma unroll
            for (int j = 0; j < 8; ++j) MMA(C[0][j], ah[0], bh[2 * j], bh[2 * j + 1]);
#pragma unroll
            for (int j = 0; j < 8; ++j) MMA(C[1][j], ah[1], bh[2 * j], bh[2 * j + 1]);
            // al x bh sweeps (bh still live), then lo-level B
#pragma unroll
            for (int j = 0; j < 8; ++j) MMA(Clo[0][j], al[0], bh[2 * j], bh[2 * j + 1]);
#pragma unroll
            for (int j = 0; j < 8; ++j) MMA(Clo[1][j], al[1], bh[2 * j], bh[2 * j + 1]);
            unsigned bl[16];
#pragma unroll
            for (int p = 0; p < 4; ++p) LDSM4(bl + 4 * p, ba + p * (16 * BPITCH) + LEVSZ);
#pragma unroll
            for (int j = 0; j < 8; ++j) MMA(Clo[0][j], ah[0], bl[2 * j], bl[2 * j + 1]);
#pragma unroll
            for (int j = 0; j < 8; ++j) MMA(Clo[1][j], ah[1], bl[2 * j], bl[2 * j + 1]);
        }
    }
    __syncthreads();   // GEMM done; smem becomes reduction scratch

    // ---------------- epilogue (proven R5/R8/R10; 2 m-tiles per warp) --------
    float* s_imp = reinterpret_cast<float*>(smem);
    float* s_cnt = s_imp + NEXP;
    float* s_z   = s_cnt + NEXP;
    if (tid < NEXP) { s_imp[tid] = 0.0f; s_cnt[tid] = 0.0f; }
    if (tid == NEXP) *s_z = 0.0f;
    __syncthreads();

    const int trow = token0 + w * 32;
    float v[16], p[16], imp[16];
    float zz = 0.0f;
#pragma unroll
    for (int i = 0; i < 16; ++i) imp[i] = 0.0f;

#pragma unroll
    for (int m = 0; m < 2; ++m) {
        // row m*16+g (C lanes 0,1)
#pragma unroll
        for (int j = 0; j < 8; ++j) {
            v[2 * j]     = fmaf(Clo[m][j][0], INVSCALE, C[m][j][0]);
            v[2 * j + 1] = fmaf(Clo[m][j][1], INVSCALE, C[m][j][1]);
        }
        row_epilogue(v, p, trow + m * 16 + g, qc, lane, out, s_cnt, zz);
#pragma unroll
        for (int i = 0; i < 16; ++i) imp[i] += p[i];

        // row m*16+g+8 (C lanes 2,3)
#pragma unroll
        for (int j = 0; j < 8; ++j) {
            v[2 * j]     = fmaf(Clo[m][j][2], INVSCALE, C[m][j][2]);
            v[2 * j + 1] = fmaf(Clo[m][j][3], INVSCALE, C[m][j][3]);
        }
        row_epilogue(v, p, trow + m * 16 + g + 8, qc, lane, out, s_cnt, zz);
#pragma unroll
        for (int i = 0; i < 16; ++i) imp[i] += p[i];
    }

    // importance across the 8 row-groups (same lane&3)
#pragma unroll
    for (int o = 4; o <= 16; o <<= 1)
#pragma unroll
        for (int i = 0; i < 16; ++i)
            imp[i] += __shfl_xor_sync(0xffffffffu, imp[i], o);
    if (lane < 4) {
#pragma unroll
        for (int j = 0; j < 8; ++j) {
            atomicAdd(&s_imp[j * 8 + qc],     imp[2 * j]);
            atomicAdd(&s_imp[j * 8 + qc + 1], imp[2 * j + 1]);
        }
    }
#pragma unroll
    for (int o = 4; o <= 16; o <<= 1) zz += __shfl_xor_sync(0xffffffffu, zz, o);
    if (lane == 0) atomicAdd(s_z, zz);
    __syncthreads();

    if (tid < NEXP) {
        atomicAdd(&g_acc[tid], s_imp[tid]);
        atomicAdd(&g_acc[NEXP + tid], s_cnt[tid]);
    }
    if (tid == NEXP) atomicAdd(&g_acc[2 * NEXP], *s_z);

    __syncthreads();
    if (tid == 0) {
        __threadfence();
        unsigned prev = atomicAdd(&g_done, 1u);
        if (prev == NCTA - 1) {
#pragma unroll
            for (int i = 0; i < NEXP; ++i) {
                out[OFF_IMP + i]  = __ldcg(&g_acc[i]) * (1.0f / (float)NTOK);
                out[OFF_LOAD + i] = __ldcg(&g_acc[NEXP + i]) * (1.0f / (float)(2 * NTOK));
            }
            out[OFF_ZLOSS] = __ldcg(&g_acc[2 * NEXP]) * (1.0f / (float)NTOK);
        }
    }
}

// ---------------------------------------------------------------------------
extern "C" void kernel_launch(void* const* d_in, const int* in_sizes, int n_in,
                              void* d_out, int out_size) {
    const float* x = (const float*)d_in[0];   // [4,4096,4096] f32
    const float* W = (const float*)d_in[1];   // [64,4096] f32
    float* out = (float*)d_out;

    cudaFuncSetAttribute(router_kernel, cudaFuncAttributeMaxDynamicSharedMemorySize,
                         SMEM_TOTAL);

    prep_kernel<<<(NEXP * DDIM + 255) / 256, 256>>>(W);
    router_kernel<<<NCTA, THREADS, SMEM_TOTAL>>>(x, out);
}

// round 15
// speedup vs baseline: 1.1801x; 1.1801x over previous
#include <cuda_runtime.h>
#include <cuda_fp16.h>
#include <cstdint>

// Problem dims: B=4, S=4096, D=4096, E=64, K=2
#define NTOK 16384
#define DDIM 4096
#define NEXP 64
#define NGRP 1024                // 16-token groups total
#define NCTA 148                 // one CTA per SM, 1 wave
#define NW   7                   // warps per CTA (one group each)
#define THREADS (NW * 32)        // 224
#define KC   64
#define NCHUNK (DDIM / KC)       // 64
#define NSTAGE 4
// group distribution: first 136 CTAs x7 groups, last 12 x6  (136*7+12*6=1024)
#define CTA7 136

// Output layout (flattened f32): idx[2N], scores[2N], probs[64N], zloss[1], imp[64], load[64]
#define OFF_IDX     0
#define OFF_SCORES  (NTOK * 2)
#define OFF_PROBS   (NTOK * 4)
#define OFF_ZLOSS   (NTOK * 4 + NTOK * NEXP)
#define OFF_IMP     (OFF_ZLOSS + 1)
#define OFF_LOAD    (OFF_IMP + NEXP)

// smem staging per stage: A fp32 (112 rows x pitch 288B) + B fp16 2 levels (pitch 144B)
#define APITCH 288
#define AROWS  112
#define ASTAGE (AROWS * APITCH)      // 32256
#define BPITCH 144
#define LEVSZ  (NEXP * BPITCH)       // 9216
#define BSTAGE (2 * LEVSZ)           // 18432
#define STAGE  (ASTAGE + BSTAGE)     // 50688
#define SMEM_TOTAL (NSTAGE * STAGE)  // 202752 <= 227KB

#define SCALE   4096.0f
#define INVSCALE (1.0f / 4096.0f)

// Scratch globals
__device__ unsigned short g_Wh[NEXP * DDIM];
__device__ unsigned short g_Wl[NEXP * DDIM];
__device__ float g_acc[2 * NEXP + 1];
__device__ unsigned int g_done;

// ---------------------------------------------------------------------------
__device__ __forceinline__ uint32_t smem_u32(const void* p) {
    uint32_t a;
    asm("{ .reg .u64 t; cvta.to.shared.u64 t, %1; cvt.u32.u64 %0, t; }" : "=r"(a) : "l"(p));
    return a;
}

#define CPA16(sm, gp) \
    asm volatile("cp.async.cg.shared.global [%0], [%1], 16;" :: "r"(sm), "l"(gp))
#define CPC()  asm volatile("cp.async.commit_group;" ::: "memory")
#define CPW2() asm volatile("cp.async.wait_group 2;" ::: "memory")
#define CPW1() asm volatile("cp.async.wait_group 1;" ::: "memory")
#define CPW0() asm volatile("cp.async.wait_group 0;" ::: "memory")

#define LDSM4(R, a) \
    asm volatile("ldmatrix.sync.aligned.m8n8.x4.shared.b16 {%0,%1,%2,%3}, [%4];" \
        : "=r"((R)[0]), "=r"((R)[1]), "=r"((R)[2]), "=r"((R)[3]) : "r"(a))

#define MMA(C, A, B0, B1) \
    asm volatile("mma.sync.aligned.m16n8k16.row.col.f32.f16.f16.f32 " \
        "{%0,%1,%2,%3}, {%4,%5,%6,%7}, {%8,%9}, {%0,%1,%2,%3};" \
        : "+f"((C)[0]), "+f"((C)[1]), "+f"((C)[2]), "+f"((C)[3]) \
        : "r"((A)[0]), "r"((A)[1]), "r"((A)[2]), "r"((A)[3]), "r"(B0), "r"(B1))

__device__ __forceinline__ void splitAx(float2 v, unsigned& h, unsigned& l) {
    __half2 hh = __float22half2_rn(v);
    float2 back = __half22float2(hh);
    float2 r = make_float2((v.x - back.x) * SCALE, (v.y - back.y) * SCALE);
    __half2 ll = __float22half2_rn(r);
    h = *reinterpret_cast<unsigned*>(&hh);
    l = *reinterpret_cast<unsigned*>(&ll);
}

__device__ __forceinline__ bool better(float v1, int i1, float v2, int i2) {
    return (v1 > v2) || (v1 == v2 && i1 < i2);
}

// ---------------------------------------------------------------------------
// Kernel 1: split W into fp16 high + scaled-residual levels; zero accumulators
// ---------------------------------------------------------------------------
__global__ void prep_kernel(const float* __restrict__ W) {
    int i = blockIdx.x * 256 + threadIdx.x;
    if (i < NEXP * DDIM) {
        float w = W[i];
        __half h = __float2half_rn(w);
        float r = (w - __half2float(h)) * SCALE;
        __half l = __float2half_rn(r);
        g_Wh[i] = *reinterpret_cast<unsigned short*>(&h);
        g_Wl[i] = *reinterpret_cast<unsigned short*>(&l);
    }
    if (i < 2 * NEXP + 1) g_acc[i] = 0.0f;
    if (i == 0) g_done = 0u;
}

// ---------------------------------------------------------------------------
// per-token-row routing epilogue (quad of 4 lanes owns one row of 64 logits)
// ---------------------------------------------------------------------------
__device__ __forceinline__ void row_epilogue(const float v[16], float p[16],
                                             int token, int qc, int lane,
                                             float* __restrict__ out,
                                             float* s_cnt, float& zz) {
    float mx = v[0];
#pragma unroll
    for (int i = 1; i < 16; ++i) mx = fmaxf(mx, v[i]);
    mx = fmaxf(mx, __shfl_xor_sync(0xffffffffu, mx, 1));
    mx = fmaxf(mx, __shfl_xor_sync(0xffffffffu, mx, 2));
    float s = 0.0f;
#pragma unroll
    for (int i = 0; i < 16; ++i) { p[i] = __expf(v[i] - mx); s += p[i]; }
    s += __shfl_xor_sync(0xffffffffu, s, 1);
    s += __shfl_xor_sync(0xffffffffu, s, 2);
    const float inv = 1.0f / s;
#pragma unroll
    for (int i = 0; i < 16; ++i) p[i] *= inv;
    float* po = out + OFF_PROBS + (size_t)token * NEXP;
#pragma unroll
    for (int j = 0; j < 8; ++j)
        *reinterpret_cast<float2*>(po + j * 8 + qc) = make_float2(p[2 * j], p[2 * j + 1]);
    // local top-2 (ascending col order; strict > keeps lowest index on ties)
    float av = -3.4e38f, bv = -3.4e38f; int ai = 0, bi = 0;
#pragma unroll
    for (int j = 0; j < 8; ++j)
#pragma unroll
        for (int i = 0; i < 2; ++i) {
            float val = v[j * 2 + i];
            int col = j * 8 + qc + i;
            if (val > av)      { bv = av; bi = ai; av = val; ai = col; }
            else if (val > bv) { bv = val; bi = col; }
        }
#pragma unroll
    for (int o = 1; o <= 2; o <<= 1) {
        float av2 = __shfl_xor_sync(0xffffffffu, av, o);
        int   ai2 = __shfl_xor_sync(0xffffffffu, ai, o);
        float bv2 = __shfl_xor_sync(0xffffffffu, bv, o);
        int   bi2 = __shfl_xor_sync(0xffffffffu, bi, o);
        if (better(av2, ai2, av, ai)) {
            bool s2 = better(bv2, bi2, av, ai);
            float nbv = s2 ? bv2 : av; int nbi = s2 ? bi2 : ai;
            av = av2; ai = ai2; bv = nbv; bi = nbi;
        } else if (better(av2, ai2, bv, bi)) { bv = av2; bi = ai2; }
    }
    if ((lane & 3) == 0) {
        float ex  = __expf(bv - av);
        float sc0 = 1.0f / (1.0f + ex);
        out[OFF_IDX + token * 2]        = (float)ai;
        out[OFF_IDX + token * 2 + 1]    = (float)bi;
        out[OFF_SCORES + token * 2]     = sc0;
        out[OFF_SCORES + token * 2 + 1] = ex * sc0;
        atomicAdd(&s_cnt[ai], 1.0f);
        atomicAdd(&s_cnt[bi], 1.0f);
    }
    float z = mx + __logf(s);
    zz += z * z;
}

// ---------------------------------------------------------------------------
// Kernel 2: fused 3-way fp16-split GEMM (mma.sync) + routing epilogue.
// Grid = 148 (one CTA per SM), 7 warps, warp = one 16-token group x 64 experts.
// First 136 CTAs carry 7 groups, last 12 carry 6 (warp 6 compute-idle but
// participates in all barriers / cp.async issue). Per-warp hot loop and memory
// pipeline identical to the round-10 winner.
// ---------------------------------------------------------------------------
__global__ void __launch_bounds__(THREADS, 1)
router_kernel(const float* __restrict__ x, float* __restrict__ out) {
    extern __shared__ __align__(16) char smem[];
    const uint32_t sb = smem_u32(smem);
    const int tid = threadIdx.x, w = tid >> 5, lane = tid & 31;
    const int g = lane >> 2, qc = (lane & 3) * 2;

    const int b = blockIdx.x;
    const int ng = (b < CTA7) ? 7 : 6;                       // groups this CTA
    const int g0 = (b < CTA7) ? 7 * b : 7 * CTA7 + 6 * (b - CTA7);
    const int token0 = g0 * 16;
    const int nrows = ng * 16;

    const char* xbytes = reinterpret_cast<const char*>(x);
    const char* whb = reinterpret_cast<const char*>(g_Wh);
    const char* wlb = reinterpret_cast<const char*>(g_Wl);

    // ldmatrix per-lane address component (layout proven rounds 3/5/8/10)
    const int n_in = (lane & 7) | ((lane & 16) >> 1);
    const int lmoff = n_in * BPITCH + ((lane & 8) << 1);

    // A fragment smem addresses (local rows w*16+g and +8)
    const uint32_t arow0 = sb + (uint32_t)(w * 16 + g) * APITCH + (uint32_t)qc * 4;
    const uint32_t arow1 = arow0 + 8u * APITCH;

    float C[8][4], Clo[8][4];
#pragma unroll
    for (int j = 0; j < 8; ++j)
#pragma unroll
        for (int i = 0; i < 4; ++i) { C[j][i] = 0.0f; Clo[j][i] = 0.0f; }

    // A: nrows*16 <= 1792 16B segs/stage, 8/thread (src row clamped; dst unique).
    // B: 1024 segs (2 levels), 5 iters predicated.
#define ISSUE_STAGE(sidx, k0)                                                        \
    do {                                                                             \
        const uint32_t _stg = sb + (uint32_t)(sidx) * STAGE;                         \
        const uint32_t _sbB = _stg + ASTAGE;                                         \
        _Pragma("unroll")                                                            \
        for (int ps = 0; ps < 8; ++ps) {                                             \
            int idx = tid + ps * THREADS;                                            \
            int row = idx >> 4, seg = idx & 15;                                      \
            int rc = row < nrows ? row : nrows - 1;                                  \
            CPA16(_stg + row * APITCH + seg * 16,                                    \
                  xbytes + ((size_t)(token0 + rc) * DDIM + (k0) + seg * 4) * 4);     \
        }                                                                            \
        _Pragma("unroll")                                                            \
        for (int ps = 0; ps < 5; ++ps) {                                             \
            int idx = tid + ps * THREADS;                                            \
            if (idx < 1024) {                                                        \
                int lev = idx >> 9, rem = idx & 511, row = rem >> 3, seg = rem & 7;  \
                const char* src = (lev == 0 ? whb : wlb)                             \
                                  + ((size_t)row * DDIM + (k0) + seg * 8) * 2;       \
                CPA16(_sbB + lev * LEVSZ + row * BPITCH + seg * 16, src);            \
            }                                                                        \
        }                                                                            \
        CPC();                                                                       \
    } while (0)

    // prologue: stages 0, 1
    ISSUE_STAGE(0, 0);
    ISSUE_STAGE(1, KC);

#pragma unroll 1
    for (int c = 0; c < NCHUNK; ++c) {
        const int bufc = c & 3;
        if (c + 2 < NCHUNK) {
            ISSUE_STAGE((c + 2) & 3, (c + 2) * KC);
            CPW2();
        } else if (c + 1 < NCHUNK) {
            CPW1();
        } else {
            CPW0();
        }
        __syncthreads();

        if (w < ng) {
            const uint32_t stg = sb + (uint32_t)bufc * STAGE;
            const uint32_t a0 = arow0 + (uint32_t)bufc * STAGE;
            const uint32_t a1 = arow1 + (uint32_t)bufc * STAGE;
            const uint32_t bbase = stg + ASTAGE + lmoff;

            // prepare ALL A fragments for this chunk (batched; proven R10)
            unsigned ah[4][4], al[4][4];
#pragma unroll
            for (int ks = 0; ks < 4; ++ks) {
                float2 f0, f1, f2, f3;
                const uint32_t ka = (uint32_t)(ks * 64);
                asm volatile("ld.shared.v2.f32 {%0,%1}, [%2];" : "=f"(f0.x), "=f"(f0.y) : "r"(a0 + ka));
                asm volatile("ld.shared.v2.f32 {%0,%1}, [%2];" : "=f"(f1.x), "=f"(f1.y) : "r"(a1 + ka));
                asm volatile("ld.shared.v2.f32 {%0,%1}, [%2];" : "=f"(f2.x), "=f"(f2.y) : "r"(a0 + ka + 32));
                asm volatile("ld.shared.v2.f32 {%0,%1}, [%2];" : "=f"(f3.x), "=f"(f3.y) : "r"(a1 + ka + 32));
                splitAx(f0, ah[ks][0], al[ks][0]);
                splitAx(f1, ah[ks][1], al[ks][1]);
                splitAx(f2, ah[ks][2], al[ks][2]);
                splitAx(f3, ah[ks][3], al[ks][3]);
            }

            // MMA stream: LDSM staggered across the three sweeps (proven R10)
#pragma unroll
            for (int ks = 0; ks < 4; ++ks) {
                const uint32_t ba = bbase + ks * 32;
                unsigned bh[16];
#pragma unroll
                for (int p = 0; p < 4; ++p) LDSM4(bh + 4 * p, ba + p * (16 * BPITCH));
#pragma unroll
                for (int j = 0; j < 8; ++j) MMA(C[j], ah[ks], bh[2 * j], bh[2 * j + 1]);
                unsigned bl[16];
#pragma unroll
                for (int p = 0; p < 4; ++p) LDSM4(bl + 4 * p, ba + p * (16 * BPITCH) + LEVSZ);
#pragma unroll
                for (int j = 0; j < 8; ++j) MMA(Clo[j], al[ks], bh[2 * j], bh[2 * j + 1]);
#pragma unroll
                for (int j = 0; j < 8; ++j) MMA(Clo[j], ah[ks], bl[2 * j], bl[2 * j + 1]);
            }
        }
    }
    __syncthreads();   // GEMM done; smem becomes reduction scratch

    // ---------------- epilogue (proven R5/R8/R10) ----------------
    float* s_imp = reinterpret_cast<float*>(smem);
    float* s_cnt = s_imp + NEXP;
    float* s_z   = s_cnt + NEXP;
    if (tid < NEXP) { s_imp[tid] = 0.0f; s_cnt[tid] = 0.0f; }
    if (tid == NEXP) *s_z = 0.0f;
    __syncthreads();

    if (w < ng) {
        const int token_r0 = token0 + w * 16 + g;
        float v[16], p[16], imp[16];
        float zz = 0.0f;
#pragma unroll
        for (int i = 0; i < 16; ++i) imp[i] = 0.0f;

        // row g (C lanes 0,1)
#pragma unroll
        for (int j = 0; j < 8; ++j) {
            v[2 * j]     = fmaf(Clo[j][0], INVSCALE, C[j][0]);
            v[2 * j + 1] = fmaf(Clo[j][1], INVSCALE, C[j][1]);
        }
        row_epilogue(v, p, token_r0, qc, lane, out, s_cnt, zz);
#pragma unroll
        for (int i = 0; i < 16; ++i) imp[i] += p[i];

        // row g+8 (C lanes 2,3)
#pragma unroll
        for (int j = 0; j < 8; ++j) {
            v[2 * j]     = fmaf(Clo[j][2], INVSCALE, C[j][2]);
            v[2 * j + 1] = fmaf(Clo[j][3], INVSCALE, C[j][3]);
        }
        row_epilogue(v, p, token_r0 + 8, qc, lane, out, s_cnt, zz);
#pragma unroll
        for (int i = 0; i < 16; ++i) imp[i] += p[i];

        // importance across the 8 row-groups (same lane&3)
#pragma unroll
        for (int o = 4; o <= 16; o <<= 1)
#pragma unroll
            for (int i = 0; i < 16; ++i)
                imp[i] += __shfl_xor_sync(0xffffffffu, imp[i], o);
        if (lane < 4) {
#pragma unroll
            for (int j = 0; j < 8; ++j) {
                atomicAdd(&s_imp[j * 8 + qc],     imp[2 * j]);
                atomicAdd(&s_imp[j * 8 + qc + 1], imp[2 * j + 1]);
            }
        }
#pragma unroll
        for (int o = 4; o <= 16; o <<= 1) zz += __shfl_xor_sync(0xffffffffu, zz, o);
        if (lane == 0) atomicAdd(s_z, zz);
    }
    __syncthreads();

    if (tid < NEXP) {
        atomicAdd(&g_acc[tid], s_imp[tid]);
        atomicAdd(&g_acc[NEXP + tid], s_cnt[tid]);
    }
    if (tid == NEXP) atomicAdd(&g_acc[2 * NEXP], *s_z);

    __syncthreads();
    if (tid == 0) {
        __threadfence();
        unsigned prev = atomicAdd(&g_done, 1u);
        if (prev == NCTA - 1) {
#pragma unroll
            for (int i = 0; i < NEXP; ++i) {
                out[OFF_IMP + i]  = __ldcg(&g_acc[i]) * (1.0f / (float)NTOK);
                out[OFF_LOAD + i] = __ldcg(&g_acc[NEXP + i]) * (1.0f / (float)(2 * NTOK));
            }
            out[OFF_ZLOSS] = __ldcg(&g_acc[2 * NEXP]) * (1.0f / (float)NTOK);
        }
    }
}

// ---------------------------------------------------------------------------
extern "C" void kernel_launch(void* const* d_in, const int* in_sizes, int n_in,
                              void* d_out, int out_size) {
    const float* x = (const float*)d_in[0];   // [4,4096,4096] f32
    const float* W = (const float*)d_in[1];   // [64,4096] f32
    float* out = (float*)d_out;

    cudaFuncSetAttribute(router_kernel, cudaFuncAttributeMaxDynamicSharedMemorySize,
                         SMEM_TOTAL);

    prep_kernel<<<(NEXP * DDIM + 255) / 256, 256>>>(W);
    router_kernel<<<NCTA, THREADS, SMEM_TOTAL>>>(x, out);
}